// round 6
// baseline (speedup 1.0000x reference)
#include <cuda_runtime.h>
#include <cuda_bf16.h>

#define Dm 128
#define EPSn 1e-5f

// ---------------- device scratch (no allocs allowed) ----------------
__device__ float g_tf[100000 * 128];
__device__ __align__(256) __nv_bfloat16 g_W1t_h[128 * 256];  // W_ctx1^T perm
__device__ __align__(256) __nv_bfloat16 g_W1t_l[128 * 256];
__device__ __align__(256) __nv_bfloat16 g_W2t_h[128 * 128];  // W_ctx2^T perm
__device__ __align__(256) __nv_bfloat16 g_W2t_l[128 * 128];
__device__ __align__(256) __nv_bfloat16 g_Wint_h[128 * 128]; // W_in^T perm
__device__ __align__(256) __nv_bfloat16 g_Wint_l[128 * 128];
__device__ __align__(256) __nv_bfloat16 g_Wm1t_h[128 * 128]; // W_m1^T perm
__device__ __align__(256) __nv_bfloat16 g_Wm1t_l[128 * 128];
__device__ __align__(256) __nv_bfloat16 g_Wm2t_h[128 * 128]; // W_m2^T perm
__device__ __align__(256) __nv_bfloat16 g_Wm2t_l[128 * 128];

__device__ __forceinline__ unsigned su32(const void* p) {
    unsigned a;
    asm("{ .reg .u64 t; cvta.to.shared.u64 t, %1; cvt.u32.u64 %0, t; }"
        : "=r"(a) : "l"(p));
    return a;
}

// word permutation: within each 8-word group, orig word w -> pos so that
// (t, t+4) land adjacent
__device__ __forceinline__ unsigned permw(unsigned w) {
    return (w & ~7u) | ((w & 3u) << 1) | ((w >> 2) & 1u);
}

__device__ __forceinline__ void mma_bf16(float* c, unsigned a0, unsigned a1,
                                         unsigned a2, unsigned a3,
                                         unsigned b0, unsigned b1) {
    asm volatile(
        "mma.sync.aligned.m16n8k16.row.col.f32.bf16.bf16.f32 "
        "{%0,%1,%2,%3},{%4,%5,%6,%7},{%8,%9},{%0,%1,%2,%3};"
        : "+f"(c[0]), "+f"(c[1]), "+f"(c[2]), "+f"(c[3])
        : "r"(a0), "r"(a1), "r"(a2), "r"(a3), "r"(b0), "r"(b1));
}

__device__ __forceinline__ void split2(float a, float b, unsigned& h, unsigned& l) {
    __nv_bfloat16 ah = __float2bfloat16(a);
    __nv_bfloat16 bh = __float2bfloat16(b);
    __nv_bfloat16 al = __float2bfloat16(a - __bfloat162float(ah));
    __nv_bfloat16 bl = __float2bfloat16(b - __bfloat162float(bh));
    __nv_bfloat162 hp; hp.x = ah; hp.y = bh;
    __nv_bfloat162 lp; lp.x = al; lp.y = bl;
    h = *(unsigned*)&hp;
    l = *(unsigned*)&lp;
}

// shared 128x128x128 gemm pass (hi/lo 3-term), X rows pre-offset to r0
__device__ __forceinline__ void gemm_tile(const unsigned* __restrict__ xh,
                                          const unsigned* __restrict__ xl,
                                          const unsigned* __restrict__ WH,
                                          const unsigned* __restrict__ WL,
                                          int g, int t, unsigned sg,
                                          float acc[16][4]) {
#pragma unroll
    for (int ks = 0; ks < 8; ks++) {
        unsigned o = (unsigned)(8 * ks + 2 * t) ^ sg;
        uint2 Ah0 = *(const uint2*)(xh + o);        // (a0,a2) hi
        uint2 Ah1 = *(const uint2*)(xh + 512 + o);  // (a1,a3) hi
        uint2 Al0 = *(const uint2*)(xl + o);
        uint2 Al1 = *(const uint2*)(xl + 512 + o);
#pragma unroll
        for (int nb = 0; nb < 16; nb++) {
            const unsigned* wh = WH + (8 * nb + g) * 64;
            const unsigned* wl = WL + (8 * nb + g) * 64;
            uint2 Bh = *(const uint2*)(wh + o);
            uint2 Bl = *(const uint2*)(wl + o);
            mma_bf16(acc[nb], Ah0.x, Ah1.x, Ah0.y, Ah1.y, Bh.x, Bh.y);
            mma_bf16(acc[nb], Al0.x, Al1.x, Al0.y, Al1.y, Bh.x, Bh.y);
            mma_bf16(acc[nb], Ah0.x, Ah1.x, Ah0.y, Ah1.y, Bl.x, Bl.y);
        }
    }
}

// ---------------------------------------------------------------------------
// K0: split/transpose all weights to bf16 hi/lo, [n][k] with permuted k-words
// ---------------------------------------------------------------------------
extern "C" __global__ void k0_prep(const float* __restrict__ Win,
                                   const float* __restrict__ W1,
                                   const float* __restrict__ W2,
                                   const float* __restrict__ Wm1,
                                   const float* __restrict__ Wm2) {
    int i = blockIdx.x * blockDim.x + threadIdx.x;
    if (i < 128 * 256) {
        int n = i >> 8, k = i & 255;
        int d = n * 256 + (int)((permw((unsigned)(k >> 1)) << 1) | (k & 1));
        float v = W1[k * 128 + n];
        __nv_bfloat16 h = __float2bfloat16(v);
        g_W1t_h[d] = h;
        g_W1t_l[d] = __float2bfloat16(v - __bfloat162float(h));
    }
    if (i < 128 * 128) {
        int n = i >> 7, k = i & 127;
        int d = n * 128 + (int)((permw((unsigned)(k >> 1)) << 1) | (k & 1));
        float v2 = W2[k * 128 + n];
        __nv_bfloat16 h2 = __float2bfloat16(v2);
        g_W2t_h[d] = h2;
        g_W2t_l[d] = __float2bfloat16(v2 - __bfloat162float(h2));
        float vi = Win[k * 128 + n];
        __nv_bfloat16 hi_ = __float2bfloat16(vi);
        g_Wint_h[d] = hi_;
        g_Wint_l[d] = __float2bfloat16(vi - __bfloat162float(hi_));
        float v3 = Wm1[k * 128 + n];
        __nv_bfloat16 h3 = __float2bfloat16(v3);
        g_Wm1t_h[d] = h3;
        g_Wm1t_l[d] = __float2bfloat16(v3 - __bfloat162float(h3));
        float v4 = Wm2[k * 128 + n];
        __nv_bfloat16 h4 = __float2bfloat16(v4);
        g_Wm2t_h[d] = h4;
        g_Wm2t_l[d] = __float2bfloat16(v4 - __bfloat162float(h4));
    }
}

// stage a 128x64-word weight array into smem with row swizzle
__device__ __forceinline__ void stageW(unsigned* dstH, unsigned* dstL,
                                       const __nv_bfloat16* srcH,
                                       const __nv_bfloat16* srcL, int tid) {
    const unsigned* sh = (const unsigned*)srcH;
    const unsigned* sl = (const unsigned*)srcL;
    for (int i = tid; i < 8192; i += 256) {
        int n = i >> 6, w = i & 63;
        int d = n * 64 + (w ^ ((n & 7) << 2));
        dstH[d] = sh[i];
        dstL[d] = sl[i];
    }
}

// ---------------------------------------------------------------------------
// K1 (mma): g_tf = target_feat @ W_in.  256 thr, tile = 128 rows.
// ---------------------------------------------------------------------------
extern "C" __global__ void __launch_bounds__(256, 1)
k1mma(const float* __restrict__ tfeat, int Nt) {
    extern __shared__ char smem[];
    unsigned* XH = (unsigned*)smem;
    unsigned* XL = XH + 8192;
    unsigned* WH = XL + 8192;
    unsigned* WL = WH + 8192;

    const int tid = threadIdx.x;
    stageW(WH, WL, g_Wint_h, g_Wint_l, tid);

    const int warp = tid >> 5, lane = tid & 31;
    const int g = lane >> 2, t = lane & 3;
    const int r0 = warp * 16 + g;
    const unsigned sg = (unsigned)(g << 2);
    const int ntiles = (Nt + 127) >> 7;
    float acc[16][4];

    __syncthreads();

    for (int tile = blockIdx.x; tile < ntiles; tile += gridDim.x) {
        const int base = tile << 7;
        // build X from tfeat rows (warp-local rows)
        {
            int row = tid >> 1, hf = tid & 1;
            int r = min(base + row, Nt - 1);
            const float4* src = (const float4*)(tfeat + (size_t)r * 128) + hf * 16;
            unsigned s = (unsigned)((row & 7) << 2);
            unsigned* xh = XH + row * 64;
            unsigned* xl = XL + row * 64;
#pragma unroll
            for (int q = 0; q < 16; q++) {
                float4 f = src[q];
                unsigned h0, l0, h1, l1;
                split2(f.x, f.y, h0, l0);
                split2(f.z, f.w, h1, l1);
                unsigned w0 = (unsigned)(hf * 32 + 2 * q);
                unsigned d0 = permw(w0) ^ s, d1 = permw(w0 + 1) ^ s;
                xh[d0] = h0; xh[d1] = h1;
                xl[d0] = l0; xl[d1] = l1;
            }
        }
        __syncwarp();
#pragma unroll
        for (int nb = 0; nb < 16; nb++) {
            acc[nb][0] = 0.f; acc[nb][1] = 0.f; acc[nb][2] = 0.f; acc[nb][3] = 0.f;
        }
        gemm_tile(XH + r0 * 64, XL + r0 * 64, WH, WL, g, t, sg, acc);
        __syncthreads();    // all warps done reading X before f32 staging overwrites
        {
            float2* sa = (float2*)smem + r0 * 64;
#pragma unroll
            for (int nb = 0; nb < 16; nb++) {
                unsigned d = (unsigned)(4 * nb + t) ^ sg;
                sa[d]       = make_float2(acc[nb][0], acc[nb][1]);
                sa[512 + d] = make_float2(acc[nb][2], acc[nb][3]);
            }
        }
        __syncthreads();
        // coalesced write to g_tf
        {
            int row = tid >> 1, hf = tid & 1;
            if (base + row < Nt) {
                unsigned s = (unsigned)((row & 7) << 2);
                const float2* rp = (const float2*)smem + row * 64;
                float4* dst = (float4*)(g_tf + (size_t)(base + row) * 128) + hf * 16;
#pragma unroll
                for (int q = 0; q < 16; q++) {
                    unsigned w = (unsigned)(hf * 32 + 2 * q);
                    float2 e0 = rp[w ^ s];
                    float2 e1 = rp[(w + 1) ^ s];
                    dst[q] = make_float4(e0.x, e0.y, e1.x, e1.y);
                }
            }
        }
        __syncthreads();
    }
}

// ---------------------------------------------------------------------------
// K2 (mma hi/lo): edge pipeline, tile = 128 edges, 256 thr, 1 CTA/SM.
// ---------------------------------------------------------------------------
extern "C" __global__ void __launch_bounds__(256, 1)
k2mma(const float* __restrict__ cfeat, const float* __restrict__ cpose,
      const float* __restrict__ tpose, const int* __restrict__ hiA,
      const int* __restrict__ wiA, const float* __restrict__ Wrp,
      const float* __restrict__ brp, const float* __restrict__ gcv,
      const float* __restrict__ bcv, int E) {
    extern __shared__ char smem[];
    unsigned* XH  = (unsigned*)smem;      // [128][64]
    unsigned* XL  = XH + 8192;
    unsigned* W1H = XL + 8192;
    unsigned* W1L = W1H + 8192;
    unsigned* W2H = W1L + 8192;
    unsigned* W2L = W2H + 8192;
    float* wrp_s = (float*)(W2L + 8192);  // 512
    float* brp_s = wrp_s + 512;
    float* gc_s  = brp_s + 128;
    float* bc_s  = gc_s + 128;
    int* hid = (int*)(bc_s + 128);
    int* wid = hid + 128;

    const int tid = threadIdx.x;
    stageW(W2H, W2L, g_W2t_h, g_W2t_l, tid);
    for (int i = tid; i < 512; i += 256) wrp_s[i] = Wrp[i];
    if (tid < 128) { brp_s[tid] = brp[tid]; gc_s[tid] = gcv[tid]; bc_s[tid] = bcv[tid]; }

    const unsigned sW1H = su32(W1H), sW1L = su32(W1L);
    auto prefetchW1 = [&](int hf) {
        const char* gH = (const char*)g_W1t_h;
        const char* gL = (const char*)g_W1t_l;
#pragma unroll
        for (int j = 0; j < 8; j++) {
            int c = tid * 8 + j;
            int n = c >> 4, w0 = (c & 15) << 2;
            unsigned dst = (unsigned)((n * 64 + (w0 ^ ((n & 7) << 2))) * 4);
            size_t src = (size_t)n * 512 + (size_t)hf * 256 + (size_t)w0 * 4;
            asm volatile("cp.async.cg.shared.global [%0], [%1], 16;"
                         :: "r"(sW1H + dst), "l"(gH + src));
            asm volatile("cp.async.cg.shared.global [%0], [%1], 16;"
                         :: "r"(sW1L + dst), "l"(gL + src));
        }
        asm volatile("cp.async.commit_group;" ::: "memory");
    };

    const int warp = tid >> 5, lane = tid & 31;
    const int g = lane >> 2, t = lane & 3;
    const int r0 = warp * 16 + g;
    const unsigned sg = (unsigned)(g << 2);
    const int ntiles = (E + 127) >> 7;
    float acc[16][4];

    prefetchW1(0);
    __syncthreads();

    for (int tile = blockIdx.x; tile < ntiles; tile += gridDim.x) {
        const int base = tile << 7;
        if (tid < 128) {
            int e = base + tid;
            int ec = e < E ? e : (E - 1);
            hid[tid] = hiA[ec];
            wid[tid] = wiA[ec];
        }
        __syncthreads();

        // ---- build x (k 0..127) = gathered context feats ----
        {
            int row = tid >> 1, hf = tid & 1;
            const float4* src = (const float4*)(cfeat + (size_t)hid[row] * 128) + hf * 16;
            unsigned s = (unsigned)((row & 7) << 2);
            unsigned* xh = XH + row * 64;
            unsigned* xl = XL + row * 64;
#pragma unroll
            for (int q = 0; q < 16; q++) {
                float4 f = src[q];
                unsigned h0, l0, h1, l1;
                split2(f.x, f.y, h0, l0);
                split2(f.z, f.w, h1, l1);
                unsigned w0 = (unsigned)(hf * 32 + 2 * q);
                unsigned d0 = permw(w0) ^ s, d1 = permw(w0 + 1) ^ s;
                xh[d0] = h0; xh[d1] = h1;
                xl[d0] = l0; xl[d1] = l1;
            }
        }
        asm volatile("cp.async.wait_group 0;" ::: "memory");
        __syncthreads();

#pragma unroll
        for (int nb = 0; nb < 16; nb++) {
            acc[nb][0] = 0.f; acc[nb][1] = 0.f; acc[nb][2] = 0.f; acc[nb][3] = 0.f;
        }
        gemm_tile(XH + r0 * 64, XL + r0 * 64, W1H, W1L, g, t, sg, acc);
        __syncthreads();
        prefetchW1(1);

        // ---- build x (k 128..255) = relpose MLP ----
        {
            int row = tid >> 1, hf = tid & 1;
            float4 cp = *(const float4*)(cpose + 4 * (size_t)hid[row]);
            float4 tp = *(const float4*)(tpose + 4 * (size_t)wid[row]);
            float d0 = cp.x - tp.x, d1 = cp.y - tp.y;
            float d2 = cp.z - tp.z, d3 = cp.w - tp.w;
            unsigned s = (unsigned)((row & 7) << 2);
            unsigned* xh = XH + row * 64;
            unsigned* xl = XL + row * 64;
#pragma unroll 8
            for (int q = 0; q < 32; q++) {
                int c0 = hf * 64 + 2 * q;
                float a = fmaxf(brp_s[c0] + d0 * wrp_s[c0] + d1 * wrp_s[128 + c0] +
                                d2 * wrp_s[256 + c0] + d3 * wrp_s[384 + c0], 0.f);
                float b = fmaxf(brp_s[c0 + 1] + d0 * wrp_s[c0 + 1] + d1 * wrp_s[128 + c0 + 1] +
                                d2 * wrp_s[256 + c0 + 1] + d3 * wrp_s[384 + c0 + 1], 0.f);
                unsigned hh, ll;
                split2(a, b, hh, ll);
                unsigned d = permw((unsigned)(hf * 32 + q)) ^ s;
                xh[d] = hh; xl[d] = ll;
            }
        }
        asm volatile("cp.async.wait_group 0;" ::: "memory");
        __syncthreads();

        gemm_tile(XH + r0 * 64, XL + r0 * 64, W1H, W1L, g, t, sg, acc);
        __syncthreads();
        prefetchW1(0);            // next tile's half0

        // ---- epilogue 1: GroupNorm + relu -> h back into XH/XL (warp-local) ----
        {
            float s1a = 0.f, s2a = 0.f, s1b = 0.f, s2b = 0.f;
#pragma unroll
            for (int nb = 0; nb < 16; nb++) {
                s1a += acc[nb][0] + acc[nb][1];
                s2a += acc[nb][0] * acc[nb][0] + acc[nb][1] * acc[nb][1];
                s1b += acc[nb][2] + acc[nb][3];
                s2b += acc[nb][2] * acc[nb][2] + acc[nb][3] * acc[nb][3];
            }
#pragma unroll
            for (int off = 1; off <= 2; off <<= 1) {
                s1a += __shfl_xor_sync(0xffffffffu, s1a, off);
                s2a += __shfl_xor_sync(0xffffffffu, s2a, off);
                s1b += __shfl_xor_sync(0xffffffffu, s1b, off);
                s2b += __shfl_xor_sync(0xffffffffu, s2b, off);
            }
            float mua = s1a * 0.0078125f;
            float rsa = rsqrtf(s2a * 0.0078125f - mua * mua + EPSn);
            float mub = s1b * 0.0078125f;
            float rsb = rsqrtf(s2b * 0.0078125f - mub * mub + EPSn);

            unsigned* xh = XH + r0 * 64;
            unsigned* xl = XL + r0 * 64;
#pragma unroll
            for (int nb = 0; nb < 16; nb++) {
                int c0 = 8 * nb + 2 * t;
                float ga = gc_s[c0], gb = gc_s[c0 + 1];
                float ba = bc_s[c0], bb = bc_s[c0 + 1];
                float h0 = fmaxf((acc[nb][0] - mua) * rsa * ga + ba, 0.f);
                float h1 = fmaxf((acc[nb][1] - mua) * rsa * gb + bb, 0.f);
                float h2 = fmaxf((acc[nb][2] - mub) * rsb * ga + ba, 0.f);
                float h3 = fmaxf((acc[nb][3] - mub) * rsb * gb + bb, 0.f);
                unsigned p0, q0, p1, q1;
                split2(h0, h1, p0, q0);
                split2(h2, h3, p1, q1);
                unsigned d = permw((unsigned)(4 * nb + t)) ^ sg;
                xh[d] = p0; xh[512 + d] = p1;
                xl[d] = q0; xl[512 + d] = q1;
            }
        }
        __syncwarp();

        // ---- GEMM2: ctx = h @ W_ctx2 ----
#pragma unroll
        for (int nb = 0; nb < 16; nb++) {
            acc[nb][0] = 0.f; acc[nb][1] = 0.f; acc[nb][2] = 0.f; acc[nb][3] = 0.f;
        }
        gemm_tile(XH + r0 * 64, XL + r0 * 64, W2H, W2L, g, t, sg, acc);
        __syncthreads();    // all warps done reading h before staging overwrite

        // ---- stage acc f32 ----
        {
            float2* sa = (float2*)smem + r0 * 64;
#pragma unroll
            for (int nb = 0; nb < 16; nb++) {
                unsigned d = (unsigned)(4 * nb + t) ^ sg;
                sa[d]       = make_float2(acc[nb][0], acc[nb][1]);
                sa[512 + d] = make_float2(acc[nb][2], acc[nb][3]);
            }
        }
        __syncthreads();

        // ---- vector scatter-add into g_tf ----
        {
            int row = tid >> 1, hq = tid & 1;
            if (base + row < E) {
                float* dst = g_tf + (size_t)wid[row] * 128;
                float2* rp = (float2*)smem + row * 64;
                unsigned s = (unsigned)((row & 7) << 2);
#pragma unroll
                for (int j = 0; j < 16; j++) {
                    int c = hq * 16 + j;
                    unsigned d2 = (unsigned)(2 * c) ^ s;
                    float4 v = *(const float4*)(rp + d2);
                    asm volatile("red.global.add.v4.f32 [%0], {%1,%2,%3,%4};"
                                 :: "l"(dst + 4 * c),
                                    "f"(v.x), "f"(v.y), "f"(v.z), "f"(v.w)
                                 : "memory");
                }
            }
        }
        __syncthreads();
    }
}

// ---------------------------------------------------------------------------
// K3 (mma): GN -> W_m1 -> GN -> W_m2 -> GN + identity + relu.
// ---------------------------------------------------------------------------
extern "C" __global__ void __launch_bounds__(256, 1)
k3mma(const float* __restrict__ tfeat,
      const float* __restrict__ gn,  const float* __restrict__ ben,
      const float* __restrict__ g1,  const float* __restrict__ b1,
      const float* __restrict__ g2,  const float* __restrict__ b2,
      float* __restrict__ out, int Nt) {
    extern __shared__ char smem[];
    unsigned* XH  = (unsigned*)smem;
    unsigned* XL  = XH + 8192;
    unsigned* W1H = XL + 8192;
    unsigned* W1L = W1H + 8192;
    unsigned* W2H = W1L + 8192;
    unsigned* W2L = W2H + 8192;
    float* ps = (float*)(W2L + 8192);   // 768

    const int tid = threadIdx.x;
    stageW(W1H, W1L, g_Wm1t_h, g_Wm1t_l, tid);
    stageW(W2H, W2L, g_Wm2t_h, g_Wm2t_l, tid);
    if (tid < 128) {
        ps[tid]       = gn[tid];  ps[128 + tid] = ben[tid];
        ps[256 + tid] = g1[tid];  ps[384 + tid] = b1[tid];
        ps[512 + tid] = g2[tid];  ps[640 + tid] = b2[tid];
    }

    const int warp = tid >> 5, lane = tid & 31;
    const int g = lane >> 2, t = lane & 3;
    const int r0 = warp * 16 + g;
    const unsigned sg = (unsigned)(g << 2);
    const int ntiles = (Nt + 127) >> 7;
    float acc[16][4];

    __syncthreads();

    for (int tile = blockIdx.x; tile < ntiles; tile += gridDim.x) {
        const int base = tile << 7;

        // ---- build: a = relu(GN(g_tf row; gn, ben)) -> X ----
        {
            int row = tid >> 1, hf = tid & 1;
            int r = min(base + row, Nt - 1);
            const float4* src = (const float4*)(g_tf + (size_t)r * 128) + hf * 16;
            float v[64];
            float s1 = 0.f, s2 = 0.f;
#pragma unroll
            for (int q = 0; q < 16; q++) {
                float4 f = src[q];
                v[4 * q] = f.x; v[4 * q + 1] = f.y; v[4 * q + 2] = f.z; v[4 * q + 3] = f.w;
                s1 += f.x + f.y + f.z + f.w;
                s2 += f.x * f.x + f.y * f.y + f.z * f.z + f.w * f.w;
            }
            s1 += __shfl_xor_sync(0xffffffffu, s1, 1);
            s2 += __shfl_xor_sync(0xffffffffu, s2, 1);
            float mu = s1 * 0.0078125f;
            float rs = rsqrtf(s2 * 0.0078125f - mu * mu + EPSn);
            unsigned s = (unsigned)((row & 7) << 2);
            unsigned* xh = XH + row * 64;
            unsigned* xl = XL + row * 64;
#pragma unroll
            for (int q = 0; q < 16; q++) {
                int c = hf * 64 + 4 * q;
                float a0 = fmaxf((v[4 * q]     - mu) * rs * ps[c]     + ps[128 + c], 0.f);
                float a1 = fmaxf((v[4 * q + 1] - mu) * rs * ps[c + 1] + ps[129 + c], 0.f);
                float a2 = fmaxf((v[4 * q + 2] - mu) * rs * ps[c + 2] + ps[130 + c], 0.f);
                float a3 = fmaxf((v[4 * q + 3] - mu) * rs * ps[c + 3] + ps[131 + c], 0.f);
                unsigned h0, l0, h1, l1;
                split2(a0, a1, h0, l0);
                split2(a2, a3, h1, l1);
                unsigned w0 = (unsigned)(hf * 32 + 2 * q);
                unsigned d0 = permw(w0) ^ s, d1 = permw(w0 + 1) ^ s;
                xh[d0] = h0; xh[d1] = h1;
                xl[d0] = l0; xl[d1] = l1;
            }
        }
        __syncwarp();

        // ---- GEMM1 + GN(g1,b1) + relu -> X ----
#pragma unroll
        for (int nb = 0; nb < 16; nb++) {
            acc[nb][0] = 0.f; acc[nb][1] = 0.f; acc[nb][2] = 0.f; acc[nb][3] = 0.f;
        }
        gemm_tile(XH + r0 * 64, XL + r0 * 64, W1H, W1L, g, t, sg, acc);
        {
            float s1a = 0.f, s2a = 0.f, s1b = 0.f, s2b = 0.f;
#pragma unroll
            for (int nb = 0; nb < 16; nb++) {
                s1a += acc[nb][0] + acc[nb][1];
                s2a += acc[nb][0] * acc[nb][0] + acc[nb][1] * acc[nb][1];
                s1b += acc[nb][2] + acc[nb][3];
                s2b += acc[nb][2] * acc[nb][2] + acc[nb][3] * acc[nb][3];
            }
#pragma unroll
            for (int off = 1; off <= 2; off <<= 1) {
                s1a += __shfl_xor_sync(0xffffffffu, s1a, off);
                s2a += __shfl_xor_sync(0xffffffffu, s2a, off);
                s1b += __shfl_xor_sync(0xffffffffu, s1b, off);
                s2b += __shfl_xor_sync(0xffffffffu, s2b, off);
            }
            float mua = s1a * 0.0078125f;
            float rsa = rsqrtf(s2a * 0.0078125f - mua * mua + EPSn);
            float mub = s1b * 0.0078125f;
            float rsb = rsqrtf(s2b * 0.0078125f - mub * mub + EPSn);

            unsigned* xh = XH + r0 * 64;
            unsigned* xl = XL + r0 * 64;
#pragma unroll
            for (int nb = 0; nb < 16; nb++) {
                int c0 = 8 * nb + 2 * t;
                float ga = ps[256 + c0], gb = ps[257 + c0];
                float ba = ps[384 + c0], bb = ps[385 + c0];
                float h0 = fmaxf((acc[nb][0] - mua) * rsa * ga + ba, 0.f);
                float h1 = fmaxf((acc[nb][1] - mua) * rsa * gb + bb, 0.f);
                float h2 = fmaxf((acc[nb][2] - mub) * rsb * ga + ba, 0.f);
                float h3 = fmaxf((acc[nb][3] - mub) * rsb * gb + bb, 0.f);
                unsigned p0, q0, p1, q1;
                split2(h0, h1, p0, q0);
                split2(h2, h3, p1, q1);
                unsigned d = permw((unsigned)(4 * nb + t)) ^ sg;
                xh[d] = p0; xh[512 + d] = p1;
                xl[d] = q0; xl[512 + d] = q1;
            }
        }
        __syncwarp();

        // ---- GEMM2, stage f32 ----
#pragma unroll
        for (int nb = 0; nb < 16; nb++) {
            acc[nb][0] = 0.f; acc[nb][1] = 0.f; acc[nb][2] = 0.f; acc[nb][3] = 0.f;
        }
        gemm_tile(XH + r0 * 64, XL + r0 * 64, W2H, W2L, g, t, sg, acc);
        __syncthreads();    // all warps done reading h before staging overwrite
        {
            float2* sa = (float2*)smem + r0 * 64;
#pragma unroll
            for (int nb = 0; nb < 16; nb++) {
                unsigned d = (unsigned)(4 * nb + t) ^ sg;
                sa[d]       = make_float2(acc[nb][0], acc[nb][1]);
                sa[512 + d] = make_float2(acc[nb][2], acc[nb][3]);
            }
        }
        __syncthreads();

        // ---- writer: GN(g2,b2) + identity + relu -> out ----
        {
            int row = tid >> 1, hf = tid & 1;
            int r = min(base + row, Nt - 1);
            unsigned s = (unsigned)((row & 7) << 2);
            const float2* rp = (const float2*)smem + row * 64;
            float2 vv[32];
            float s1 = 0.f, s2 = 0.f;
#pragma unroll
            for (int w = 0; w < 32; w++) {
                float2 e = rp[(unsigned)(32 * hf + w) ^ s];
                vv[w] = e;
                s1 += e.x + e.y;
                s2 += e.x * e.x + e.y * e.y;
            }
            s1 += __shfl_xor_sync(0xffffffffu, s1, 1);
            s2 += __shfl_xor_sync(0xffffffffu, s2, 1);
            float mu = s1 * 0.0078125f;
            float rs = rsqrtf(s2 * 0.0078125f - mu * mu + EPSn);
            if (base + row < Nt) {
                const float4* idp = (const float4*)(tfeat + (size_t)r * 128) + hf * 16;
                float4* dst = (float4*)(out + (size_t)r * 128) + hf * 16;
#pragma unroll
                for (int q = 0; q < 16; q++) {
                    int c = hf * 64 + 4 * q;
                    float4 idv = idp[q];
                    float2 e0 = vv[2 * q], e1 = vv[2 * q + 1];
                    float4 o;
                    o.x = fmaxf((e0.x - mu) * rs * ps[512 + c]     + ps[640 + c]     + idv.x, 0.f);
                    o.y = fmaxf((e0.y - mu) * rs * ps[512 + c + 1] + ps[640 + c + 1] + idv.y, 0.f);
                    o.z = fmaxf((e1.x - mu) * rs * ps[512 + c + 2] + ps[640 + c + 2] + idv.z, 0.f);
                    o.w = fmaxf((e1.y - mu) * rs * ps[512 + c + 3] + ps[640 + c + 3] + idv.w, 0.f);
                    dst[q] = o;
                }
            }
        }
        __syncthreads();
    }
}

// ---------------------------------------------------------------------------
// launch
// ---------------------------------------------------------------------------
extern "C" void kernel_launch(void* const* d_in, const int* in_sizes, int n_in,
                              void* d_out, int out_size) {
    const float* context_feat = (const float*)d_in[0];
    const float* target_feat  = (const float*)d_in[1];
    const float* context_pose = (const float*)d_in[2];
    const float* target_pose  = (const float*)d_in[3];
    const int*   hi    = (const int*)d_in[4];
    const int*   wi    = (const int*)d_in[5];
    const float* W_in  = (const float*)d_in[6];
    const float* W_rp  = (const float*)d_in[7];
    const float* b_rp  = (const float*)d_in[8];
    const float* W_c1  = (const float*)d_in[9];
    const float* g_ctx = (const float*)d_in[10];
    const float* be_ctx= (const float*)d_in[11];
    const float* W_c2  = (const float*)d_in[12];
    const float* g_n   = (const float*)d_in[13];
    const float* be_n  = (const float*)d_in[14];
    const float* W_m1  = (const float*)d_in[15];
    const float* g_m1  = (const float*)d_in[16];
    const float* be_m1 = (const float*)d_in[17];
    const float* W_m2  = (const float*)d_in[18];
    const float* g_m2  = (const float*)d_in[19];
    const float* be_m2 = (const float*)d_in[20];

    int Nt = in_sizes[1] / 128;
    int E  = in_sizes[4];
    float* out = (float*)d_out;

    const int SM1 = 4 * 32768;                    // 131072
    const int SM2 = 6 * 32768 + 896 * 4 + 1024;   // 201216
    const int SM3 = 6 * 32768 + 768 * 4;          // 199680

    cudaFuncSetAttribute(k1mma, cudaFuncAttributeMaxDynamicSharedMemorySize, SM1);
    cudaFuncSetAttribute(k2mma, cudaFuncAttributeMaxDynamicSharedMemorySize, SM2);
    cudaFuncSetAttribute(k3mma, cudaFuncAttributeMaxDynamicSharedMemorySize, SM3);

    k0_prep<<<128, 256>>>(W_in, W_c1, W_c2, W_m1, W_m2);
    k1mma<<<148, 256, SM1>>>(target_feat, Nt);
    k2mma<<<148, 256, SM2>>>(context_feat, context_pose, target_pose, hi, wi,
                             W_rp, b_rp, g_ctx, be_ctx, E);
    k3mma<<<148, 256, SM3>>>(target_feat, g_n, be_n, g_m1, be_m1, g_m2, be_m2,
                             out, Nt);
}

// round 7
// speedup vs baseline: 1.1902x; 1.1902x over previous
#include <cuda_runtime.h>
#include <cuda_bf16.h>

#define Dm 128
#define EPSn 1e-5f

// ---------------- device scratch (no allocs allowed) ----------------
__device__ float g_tf[100000 * 128];
// fragment-ordered (for k2): B frag [hf][nb][ks][lane][2]
__device__ __align__(256) __nv_bfloat16 g_W1f_h[2 * 8192 * 2];
__device__ __align__(256) __nv_bfloat16 g_W1f_l[2 * 8192 * 2];
__device__ __align__(256) __nv_bfloat16 g_W2f_h[8192 * 2];
__device__ __align__(256) __nv_bfloat16 g_W2f_l[8192 * 2];
// permw-ordered (for k1/k3)
__device__ __align__(256) __nv_bfloat16 g_Wint_h[128 * 128];
__device__ __align__(256) __nv_bfloat16 g_Wint_l[128 * 128];
__device__ __align__(256) __nv_bfloat16 g_Wm1t_h[128 * 128];
__device__ __align__(256) __nv_bfloat16 g_Wm1t_l[128 * 128];
__device__ __align__(256) __nv_bfloat16 g_Wm2t_h[128 * 128];
__device__ __align__(256) __nv_bfloat16 g_Wm2t_l[128 * 128];

__device__ __forceinline__ unsigned su32(const void* p) {
    unsigned a;
    asm("{ .reg .u64 t; cvta.to.shared.u64 t, %1; cvt.u32.u64 %0, t; }"
        : "=r"(a) : "l"(p));
    return a;
}

__device__ __forceinline__ unsigned permw(unsigned w) {
    return (w & ~7u) | ((w & 3u) << 1) | ((w >> 2) & 1u);
}

// A-fragment word index within a warp's 1024-word region: row r (0..15), word w (0..63)
__device__ __forceinline__ int aidx(int r, int w) {
    return ((w >> 3) << 7) + (((r & 7) * 4 + (w & 3)) << 2)
         + ((r >> 3) & 1) + (((w >> 2) & 1) << 1);
}

__device__ __forceinline__ void mma_bf16(float* c, unsigned a0, unsigned a1,
                                         unsigned a2, unsigned a3,
                                         unsigned b0, unsigned b1) {
    asm volatile(
        "mma.sync.aligned.m16n8k16.row.col.f32.bf16.bf16.f32 "
        "{%0,%1,%2,%3},{%4,%5,%6,%7},{%8,%9},{%0,%1,%2,%3};"
        : "+f"(c[0]), "+f"(c[1]), "+f"(c[2]), "+f"(c[3])
        : "r"(a0), "r"(a1), "r"(a2), "r"(a3), "r"(b0), "r"(b1));
}

__device__ __forceinline__ void split2(float a, float b, unsigned& h, unsigned& l) {
    __nv_bfloat16 ah = __float2bfloat16(a);
    __nv_bfloat16 bh = __float2bfloat16(b);
    __nv_bfloat16 al = __float2bfloat16(a - __bfloat162float(ah));
    __nv_bfloat16 bl = __float2bfloat16(b - __bfloat162float(bh));
    __nv_bfloat162 hp; hp.x = ah; hp.y = bh;
    __nv_bfloat162 lp; lp.x = al; lp.y = bl;
    h = *(unsigned*)&hp;
    l = *(unsigned*)&lp;
}

// fragment-ordered gemm pass: A per-warp [ks][lane][4], B [nb][ks][lane][2]
__device__ __forceinline__ void gemm_frag(const unsigned* __restrict__ xh,
                                          const unsigned* __restrict__ xl,
                                          const unsigned* __restrict__ WH,
                                          const unsigned* __restrict__ WL,
                                          int lane, float acc[16][4]) {
#pragma unroll
    for (int ks = 0; ks < 8; ks++) {
        uint4 Ah = *(const uint4*)(xh + ks * 128 + lane * 4);
        uint4 Al = *(const uint4*)(xl + ks * 128 + lane * 4);
#pragma unroll
        for (int nb = 0; nb < 16; nb++) {
            unsigned off = (unsigned)(((nb * 8 + ks) * 32 + lane) * 2);
            uint2 Bh = *(const uint2*)(WH + off);
            uint2 Bl = *(const uint2*)(WL + off);
            mma_bf16(acc[nb], Ah.x, Ah.y, Ah.z, Ah.w, Bh.x, Bh.y);
            mma_bf16(acc[nb], Al.x, Al.y, Al.z, Al.w, Bh.x, Bh.y);
            mma_bf16(acc[nb], Ah.x, Ah.y, Ah.z, Ah.w, Bl.x, Bl.y);
        }
    }
}

// permw-layout gemm pass (k1/k3, unchanged from R6)
__device__ __forceinline__ void gemm_tile(const unsigned* __restrict__ xh,
                                          const unsigned* __restrict__ xl,
                                          const unsigned* __restrict__ WH,
                                          const unsigned* __restrict__ WL,
                                          int g, int t, unsigned sg,
                                          float acc[16][4]) {
#pragma unroll
    for (int ks = 0; ks < 8; ks++) {
        unsigned o = (unsigned)(8 * ks + 2 * t) ^ sg;
        uint2 Ah0 = *(const uint2*)(xh + o);
        uint2 Ah1 = *(const uint2*)(xh + 512 + o);
        uint2 Al0 = *(const uint2*)(xl + o);
        uint2 Al1 = *(const uint2*)(xl + 512 + o);
#pragma unroll
        for (int nb = 0; nb < 16; nb++) {
            const unsigned* wh = WH + (8 * nb + g) * 64;
            const unsigned* wl = WL + (8 * nb + g) * 64;
            uint2 Bh = *(const uint2*)(wh + o);
            uint2 Bl = *(const uint2*)(wl + o);
            mma_bf16(acc[nb], Ah0.x, Ah1.x, Ah0.y, Ah1.y, Bh.x, Bh.y);
            mma_bf16(acc[nb], Al0.x, Al1.x, Al0.y, Al1.y, Bh.x, Bh.y);
            mma_bf16(acc[nb], Ah0.x, Ah1.x, Ah0.y, Ah1.y, Bl.x, Bl.y);
        }
    }
}

// ---------------------------------------------------------------------------
// K0: weight prep.  W1/W2 -> fragment order; Win/Wm1/Wm2 -> permw order.
// ---------------------------------------------------------------------------
extern "C" __global__ void k0_prep(const float* __restrict__ Win,
                                   const float* __restrict__ W1,
                                   const float* __restrict__ W2,
                                   const float* __restrict__ Wm1,
                                   const float* __restrict__ Wm2) {
    int i = blockIdx.x * blockDim.x + threadIdx.x;
    if (i < 128 * 256) {           // W1 frag: (n, k) k<256
        int n = i >> 8, k = i & 255;
        int w = k >> 1, ko = k & 1;
        int hf = w >> 6, wl = w & 63;
        int ks = wl >> 3, wp = wl & 7;
        int widx = hf * 8192 + (((n >> 3) * 8 + ks) * 32 + 4 * (n & 7) + (wp & 3)) * 2
                 + ((wp >> 2) & 1);
        int b = widx * 2 + ko;
        float v = W1[k * 128 + n];
        __nv_bfloat16 h = __float2bfloat16(v);
        g_W1f_h[b] = h;
        g_W1f_l[b] = __float2bfloat16(v - __bfloat162float(h));
    }
    if (i < 128 * 128) {
        int n = i >> 7, k = i & 127;
        int w = k >> 1, ko = k & 1;
        int ks = w >> 3, wp = w & 7;
        int widx = (((n >> 3) * 8 + ks) * 32 + 4 * (n & 7) + (wp & 3)) * 2 + ((wp >> 2) & 1);
        int b = widx * 2 + ko;
        float v2 = W2[k * 128 + n];
        __nv_bfloat16 h2 = __float2bfloat16(v2);
        g_W2f_h[b] = h2;
        g_W2f_l[b] = __float2bfloat16(v2 - __bfloat162float(h2));

        int d = n * 128 + (int)((permw((unsigned)w) << 1) | (unsigned)ko);
        float vi = Win[k * 128 + n];
        __nv_bfloat16 hi_ = __float2bfloat16(vi);
        g_Wint_h[d] = hi_;
        g_Wint_l[d] = __float2bfloat16(vi - __bfloat162float(hi_));
        float v3 = Wm1[k * 128 + n];
        __nv_bfloat16 h3 = __float2bfloat16(v3);
        g_Wm1t_h[d] = h3;
        g_Wm1t_l[d] = __float2bfloat16(v3 - __bfloat162float(h3));
        float v4 = Wm2[k * 128 + n];
        __nv_bfloat16 h4 = __float2bfloat16(v4);
        g_Wm2t_h[d] = h4;
        g_Wm2t_l[d] = __float2bfloat16(v4 - __bfloat162float(h4));
    }
}

// stage permw weight array into smem with row swizzle (k1/k3)
__device__ __forceinline__ void stageW(unsigned* dstH, unsigned* dstL,
                                       const __nv_bfloat16* srcH,
                                       const __nv_bfloat16* srcL, int tid) {
    const unsigned* sh = (const unsigned*)srcH;
    const unsigned* sl = (const unsigned*)srcL;
    for (int i = tid; i < 8192; i += 256) {
        int n = i >> 6, w = i & 63;
        int d = n * 64 + (w ^ ((n & 7) << 2));
        dstH[d] = sh[i];
        dstL[d] = sl[i];
    }
}

// ---------------------------------------------------------------------------
// K1 (mma, permw layout): g_tf = target_feat @ W_in
// ---------------------------------------------------------------------------
extern "C" __global__ void __launch_bounds__(256, 1)
k1mma(const float* __restrict__ tfeat, int Nt) {
    extern __shared__ char smem[];
    unsigned* XH = (unsigned*)smem;
    unsigned* XL = XH + 8192;
    unsigned* WH = XL + 8192;
    unsigned* WL = WH + 8192;

    const int tid = threadIdx.x;
    stageW(WH, WL, g_Wint_h, g_Wint_l, tid);

    const int warp = tid >> 5, lane = tid & 31;
    const int g = lane >> 2, t = lane & 3;
    const int r0 = warp * 16 + g;
    const unsigned sg = (unsigned)(g << 2);
    const int ntiles = (Nt + 127) >> 7;
    float acc[16][4];

    __syncthreads();

    for (int tile = blockIdx.x; tile < ntiles; tile += gridDim.x) {
        const int base = tile << 7;
        {
            int row = tid >> 1, hf = tid & 1;
            int r = min(base + row, Nt - 1);
            const float4* src = (const float4*)(tfeat + (size_t)r * 128) + hf * 16;
            unsigned s = (unsigned)((row & 7) << 2);
            unsigned* xh = XH + row * 64;
            unsigned* xl = XL + row * 64;
#pragma unroll
            for (int q = 0; q < 16; q++) {
                float4 f = src[q];
                unsigned h0, l0, h1, l1;
                split2(f.x, f.y, h0, l0);
                split2(f.z, f.w, h1, l1);
                unsigned w0 = (unsigned)(hf * 32 + 2 * q);
                unsigned d0 = permw(w0) ^ s, d1 = permw(w0 + 1) ^ s;
                xh[d0] = h0; xh[d1] = h1;
                xl[d0] = l0; xl[d1] = l1;
            }
        }
        __syncwarp();
#pragma unroll
        for (int nb = 0; nb < 16; nb++) {
            acc[nb][0] = 0.f; acc[nb][1] = 0.f; acc[nb][2] = 0.f; acc[nb][3] = 0.f;
        }
        gemm_tile(XH + r0 * 64, XL + r0 * 64, WH, WL, g, t, sg, acc);
        __syncthreads();
        {
            float2* sa = (float2*)smem + r0 * 64;
#pragma unroll
            for (int nb = 0; nb < 16; nb++) {
                unsigned d = (unsigned)(4 * nb + t) ^ sg;
                sa[d]       = make_float2(acc[nb][0], acc[nb][1]);
                sa[512 + d] = make_float2(acc[nb][2], acc[nb][3]);
            }
        }
        __syncthreads();
        {
            int row = tid >> 1, hf = tid & 1;
            if (base + row < Nt) {
                unsigned s = (unsigned)((row & 7) << 2);
                const float2* rp = (const float2*)smem + row * 64;
                float4* dst = (float4*)(g_tf + (size_t)(base + row) * 128) + hf * 16;
#pragma unroll
                for (int q = 0; q < 16; q++) {
                    unsigned w = (unsigned)(hf * 32 + 2 * q);
                    float2 e0 = rp[w ^ s];
                    float2 e1 = rp[(w + 1) ^ s];
                    dst[q] = make_float4(e0.x, e0.y, e1.x, e1.y);
                }
            }
        }
        __syncthreads();
    }
}

// ---------------------------------------------------------------------------
// K2 (mma, fragment-ordered, warp-local): edge pipeline.
// smem: XH/XL per-warp frag regions, W1 (streamed halves), W2 resident, params.
// ---------------------------------------------------------------------------
extern "C" __global__ void __launch_bounds__(256, 1)
k2mma(const float* __restrict__ cfeat, const float* __restrict__ cpose,
      const float* __restrict__ tpose, const int* __restrict__ hiA,
      const int* __restrict__ wiA, const float* __restrict__ Wrp,
      const float* __restrict__ brp, const float* __restrict__ gcv,
      const float* __restrict__ bcv, int E) {
    extern __shared__ char smem[];
    unsigned* XH  = (unsigned*)smem;      // 8 warps x 1024 words
    unsigned* XL  = XH + 8192;
    unsigned* W1H = XL + 8192;            // one k-half, frag order
    unsigned* W1L = W1H + 8192;
    unsigned* W2H = W1L + 8192;
    unsigned* W2L = W2H + 8192;
    float* wrp_s = (float*)(W2L + 8192);  // 512
    float* brp_s = wrp_s + 512;           // 128
    float* gc_s  = brp_s + 128;           // 128
    float* bc_s  = gc_s + 128;            // 128

    const int tid = threadIdx.x;
    // W2 frag staging: straight copy
    {
        const unsigned* sh = (const unsigned*)g_W2f_h;
        const unsigned* sl = (const unsigned*)g_W2f_l;
        for (int i = tid; i < 8192; i += 256) { W2H[i] = sh[i]; W2L[i] = sl[i]; }
    }
    for (int i = tid; i < 512; i += 256) wrp_s[i] = Wrp[i];
    if (tid < 128) { brp_s[tid] = brp[tid]; gc_s[tid] = gcv[tid]; bc_s[tid] = bcv[tid]; }

    const unsigned sW1H = su32(W1H), sW1L = su32(W1L);
    auto prefetchW1 = [&](int hf) {
        const char* gH = (const char*)g_W1f_h + (size_t)hf * 32768;
        const char* gL = (const char*)g_W1f_l + (size_t)hf * 32768;
#pragma unroll
        for (int j = 0; j < 8; j++) {
            unsigned off = (unsigned)((tid * 8 + j) * 16);
            asm volatile("cp.async.cg.shared.global [%0], [%1], 16;"
                         :: "r"(sW1H + off), "l"(gH + off));
            asm volatile("cp.async.cg.shared.global [%0], [%1], 16;"
                         :: "r"(sW1L + off), "l"(gL + off));
        }
        asm volatile("cp.async.commit_group;" ::: "memory");
    };

    const int warp = tid >> 5, lane = tid & 31;
    const int g = lane >> 2, t = lane & 3;
    unsigned* xh = XH + warp * 1024;
    unsigned* xl = XL + warp * 1024;
    const int ntiles = (E + 127) >> 7;
    float acc[16][4];

    prefetchW1(0);
    __syncthreads();

    for (int tile = blockIdx.x; tile < ntiles; tile += gridDim.x) {
        const int base = tile << 7;
        const int rme = lane >> 1;               // builder row 0..15
        const int hf2 = lane & 1;
        const int eb  = base + warp * 16;
        int myh, myw;
        {
            int e = eb + rme;
            int ec = min(e, E - 1);
            myh = hiA[ec];
            myw = wiA[ec];
        }

        // ---- build half0: gathered context feats (warp-local) ----
        {
            const float4* src = (const float4*)(cfeat + (size_t)myh * 128) + hf2 * 16;
#pragma unroll
            for (int q = 0; q < 16; q++) {
                float4 f = src[q];
                unsigned h0, l0, h1, l1;
                split2(f.x, f.y, h0, l0);
                split2(f.z, f.w, h1, l1);
                int w0 = hf2 * 32 + 2 * q;
                int i0 = aidx(rme, w0), i1 = aidx(rme, w0 + 1);
                xh[i0] = h0; xh[i1] = h1;
                xl[i0] = l0; xl[i1] = l1;
            }
        }
        __syncwarp();
        asm volatile("cp.async.wait_group 0;" ::: "memory");
        __syncthreads();    // W1 half0 landed everywhere

#pragma unroll
        for (int nb = 0; nb < 16; nb++) {
            acc[nb][0] = 0.f; acc[nb][1] = 0.f; acc[nb][2] = 0.f; acc[nb][3] = 0.f;
        }
        gemm_frag(xh, xl, W1H, W1L, lane, acc);
        __syncthreads();    // all warps done with half0 buffer
        prefetchW1(1);

        // ---- build half1: relpose MLP (warp-local) ----
        {
            float4 cp = *(const float4*)(cpose + 4 * (size_t)myh);
            float4 tp = *(const float4*)(tpose + 4 * (size_t)myw);
            float d0 = cp.x - tp.x, d1 = cp.y - tp.y;
            float d2 = cp.z - tp.z, d3 = cp.w - tp.w;
#pragma unroll 8
            for (int q = 0; q < 32; q++) {
                int w = hf2 * 32 + q;
                int c0 = 2 * w;
                float a = fmaxf(brp_s[c0] + d0 * wrp_s[c0] + d1 * wrp_s[128 + c0] +
                                d2 * wrp_s[256 + c0] + d3 * wrp_s[384 + c0], 0.f);
                float b = fmaxf(brp_s[c0 + 1] + d0 * wrp_s[c0 + 1] + d1 * wrp_s[128 + c0 + 1] +
                                d2 * wrp_s[256 + c0 + 1] + d3 * wrp_s[384 + c0 + 1], 0.f);
                unsigned hh, ll;
                split2(a, b, hh, ll);
                int i = aidx(rme, w);
                xh[i] = hh; xl[i] = ll;
            }
        }
        __syncwarp();
        asm volatile("cp.async.wait_group 0;" ::: "memory");
        __syncthreads();    // W1 half1 landed

        gemm_frag(xh, xl, W1H, W1L, lane, acc);
        __syncthreads();    // all warps done with half1
        prefetchW1(0);      // next tile's half0 — overlaps epilogue/GEMM2/scatter

        // ---- epilogue1: GroupNorm + relu -> h (own lanes, frag order) ----
        {
            float s1a = 0.f, s2a = 0.f, s1b = 0.f, s2b = 0.f;
#pragma unroll
            for (int nb = 0; nb < 16; nb++) {
                s1a += acc[nb][0] + acc[nb][1];
                s2a += acc[nb][0] * acc[nb][0] + acc[nb][1] * acc[nb][1];
                s1b += acc[nb][2] + acc[nb][3];
                s2b += acc[nb][2] * acc[nb][2] + acc[nb][3] * acc[nb][3];
            }
#pragma unroll
            for (int off = 1; off <= 2; off <<= 1) {
                s1a += __shfl_xor_sync(0xffffffffu, s1a, off);
                s2a += __shfl_xor_sync(0xffffffffu, s2a, off);
                s1b += __shfl_xor_sync(0xffffffffu, s1b, off);
                s2b += __shfl_xor_sync(0xffffffffu, s2b, off);
            }
            float mua = s1a * 0.0078125f;
            float rsa = rsqrtf(s2a * 0.0078125f - mua * mua + EPSn);
            float mub = s1b * 0.0078125f;
            float rsb = rsqrtf(s2b * 0.0078125f - mub * mub + EPSn);
#pragma unroll
            for (int nb = 0; nb < 16; nb++) {
                int c0 = 8 * nb + 2 * t;
                float ga = gc_s[c0], gb = gc_s[c0 + 1];
                float ba = bc_s[c0], bb = bc_s[c0 + 1];
                float h0 = fmaxf((acc[nb][0] - mua) * rsa * ga + ba, 0.f);
                float h1 = fmaxf((acc[nb][1] - mua) * rsa * gb + bb, 0.f);
                float h2 = fmaxf((acc[nb][2] - mub) * rsb * ga + ba, 0.f);
                float h3 = fmaxf((acc[nb][3] - mub) * rsb * gb + bb, 0.f);
                unsigned p0, q0, p8, q8;
                split2(h0, h1, p0, q0);
                split2(h2, h3, p8, q8);
                int bi = aidx(g, 4 * nb + t);     // row g -> slot bit0 = 0
                xh[bi] = p0; xh[bi + 1] = p8;
                xl[bi] = q0; xl[bi + 1] = q8;
            }
        }
        __syncwarp();

        // ---- GEMM2 (W2 resident) ----
#pragma unroll
        for (int nb = 0; nb < 16; nb++) {
            acc[nb][0] = 0.f; acc[nb][1] = 0.f; acc[nb][2] = 0.f; acc[nb][3] = 0.f;
        }
        gemm_frag(xh, xl, W2H, W2L, lane, acc);

        // ---- direct register scatter-add into g_tf ----
        {
            int widg  = __shfl_sync(0xffffffffu, myw, 2 * g);
            int widg8 = __shfl_sync(0xffffffffu, myw, 2 * g + 16);
            bool vg  = (eb + g) < E;
            bool vg8 = (eb + g + 8) < E;
            float* d0 = g_tf + (size_t)widg * 128 + 2 * t;
            float* d8 = g_tf + (size_t)widg8 * 128 + 2 * t;
#pragma unroll
            for (int nb = 0; nb < 16; nb++) {
                if (vg)
                    asm volatile("red.global.add.v2.f32 [%0], {%1,%2};"
                                 :: "l"(d0 + 8 * nb), "f"(acc[nb][0]), "f"(acc[nb][1])
                                 : "memory");
                if (vg8)
                    asm volatile("red.global.add.v2.f32 [%0], {%1,%2};"
                                 :: "l"(d8 + 8 * nb), "f"(acc[nb][2]), "f"(acc[nb][3])
                                 : "memory");
            }
        }
    }
}

// ---------------------------------------------------------------------------
// K3 (mma, permw layout): GN -> W_m1 -> GN -> W_m2 -> GN + identity + relu.
// ---------------------------------------------------------------------------
extern "C" __global__ void __launch_bounds__(256, 1)
k3mma(const float* __restrict__ tfeat,
      const float* __restrict__ gn,  const float* __restrict__ ben,
      const float* __restrict__ g1,  const float* __restrict__ b1,
      const float* __restrict__ g2,  const float* __restrict__ b2,
      float* __restrict__ out, int Nt) {
    extern __shared__ char smem[];
    unsigned* XH  = (unsigned*)smem;
    unsigned* XL  = XH + 8192;
    unsigned* W1H = XL + 8192;
    unsigned* W1L = W1H + 8192;
    unsigned* W2H = W1L + 8192;
    unsigned* W2L = W2H + 8192;
    float* ps = (float*)(W2L + 8192);   // 768

    const int tid = threadIdx.x;
    stageW(W1H, W1L, g_Wm1t_h, g_Wm1t_l, tid);
    stageW(W2H, W2L, g_Wm2t_h, g_Wm2t_l, tid);
    if (tid < 128) {
        ps[tid]       = gn[tid];  ps[128 + tid] = ben[tid];
        ps[256 + tid] = g1[tid];  ps[384 + tid] = b1[tid];
        ps[512 + tid] = g2[tid];  ps[640 + tid] = b2[tid];
    }

    const int warp = tid >> 5, lane = tid & 31;
    const int g = lane >> 2, t = lane & 3;
    const int r0 = warp * 16 + g;
    const unsigned sg = (unsigned)(g << 2);
    const int ntiles = (Nt + 127) >> 7;
    float acc[16][4];

    __syncthreads();

    for (int tile = blockIdx.x; tile < ntiles; tile += gridDim.x) {
        const int base = tile << 7;
        {
            int row = tid >> 1, hf = tid & 1;
            int r = min(base + row, Nt - 1);
            const float4* src = (const float4*)(g_tf + (size_t)r * 128) + hf * 16;
            float v[64];
            float s1 = 0.f, s2 = 0.f;
#pragma unroll
            for (int q = 0; q < 16; q++) {
                float4 f = src[q];
                v[4 * q] = f.x; v[4 * q + 1] = f.y; v[4 * q + 2] = f.z; v[4 * q + 3] = f.w;
                s1 += f.x + f.y + f.z + f.w;
                s2 += f.x * f.x + f.y * f.y + f.z * f.z + f.w * f.w;
            }
            s1 += __shfl_xor_sync(0xffffffffu, s1, 1);
            s2 += __shfl_xor_sync(0xffffffffu, s2, 1);
            float mu = s1 * 0.0078125f;
            float rs = rsqrtf(s2 * 0.0078125f - mu * mu + EPSn);
            unsigned s = (unsigned)((row & 7) << 2);
            unsigned* xh = XH + row * 64;
            unsigned* xl = XL + row * 64;
#pragma unroll
            for (int q = 0; q < 16; q++) {
                int c = hf * 64 + 4 * q;
                float a0 = fmaxf((v[4 * q]     - mu) * rs * ps[c]     + ps[128 + c], 0.f);
                float a1 = fmaxf((v[4 * q + 1] - mu) * rs * ps[c + 1] + ps[129 + c], 0.f);
                float a2 = fmaxf((v[4 * q + 2] - mu) * rs * ps[c + 2] + ps[130 + c], 0.f);
                float a3 = fmaxf((v[4 * q + 3] - mu) * rs * ps[c + 3] + ps[131 + c], 0.f);
                unsigned h0, l0, h1, l1;
                split2(a0, a1, h0, l0);
                split2(a2, a3, h1, l1);
                unsigned w0 = (unsigned)(hf * 32 + 2 * q);
                unsigned d0 = permw(w0) ^ s, d1 = permw(w0 + 1) ^ s;
                xh[d0] = h0; xh[d1] = h1;
                xl[d0] = l0; xl[d1] = l1;
            }
        }
        __syncwarp();

#pragma unroll
        for (int nb = 0; nb < 16; nb++) {
            acc[nb][0] = 0.f; acc[nb][1] = 0.f; acc[nb][2] = 0.f; acc[nb][3] = 0.f;
        }
        gemm_tile(XH + r0 * 64, XL + r0 * 64, W1H, W1L, g, t, sg, acc);
        {
            float s1a = 0.f, s2a = 0.f, s1b = 0.f, s2b = 0.f;
#pragma unroll
            for (int nb = 0; nb < 16; nb++) {
                s1a += acc[nb][0] + acc[nb][1];
                s2a += acc[nb][0] * acc[nb][0] + acc[nb][1] * acc[nb][1];
                s1b += acc[nb][2] + acc[nb][3];
                s2b += acc[nb][2] * acc[nb][2] + acc[nb][3] * acc[nb][3];
            }
#pragma unroll
            for (int off = 1; off <= 2; off <<= 1) {
                s1a += __shfl_xor_sync(0xffffffffu, s1a, off);
                s2a += __shfl_xor_sync(0xffffffffu, s2a, off);
                s1b += __shfl_xor_sync(0xffffffffu, s1b, off);
                s2b += __shfl_xor_sync(0xffffffffu, s2b, off);
            }
            float mua = s1a * 0.0078125f;
            float rsa = rsqrtf(s2a * 0.0078125f - mua * mua + EPSn);
            float mub = s1b * 0.0078125f;
            float rsb = rsqrtf(s2b * 0.0078125f - mub * mub + EPSn);
            unsigned* xh = XH + r0 * 64;
            unsigned* xl = XL + r0 * 64;
#pragma unroll
            for (int nb = 0; nb < 16; nb++) {
                int c0 = 8 * nb + 2 * t;
                float ga = ps[256 + c0], gb = ps[257 + c0];
                float ba = ps[384 + c0], bb = ps[385 + c0];
                float h0 = fmaxf((acc[nb][0] - mua) * rsa * ga + ba, 0.f);
                float h1 = fmaxf((acc[nb][1] - mua) * rsa * gb + bb, 0.f);
                float h2 = fmaxf((acc[nb][2] - mub) * rsb * ga + ba, 0.f);
                float h3 = fmaxf((acc[nb][3] - mub) * rsb * gb + bb, 0.f);
                unsigned p0, q0, p1, q1;
                split2(h0, h1, p0, q0);
                split2(h2, h3, p1, q1);
                unsigned d = permw((unsigned)(4 * nb + t)) ^ sg;
                xh[d] = p0; xh[512 + d] = p1;
                xl[d] = q0; xl[512 + d] = q1;
            }
        }
        __syncwarp();

#pragma unroll
        for (int nb = 0; nb < 16; nb++) {
            acc[nb][0] = 0.f; acc[nb][1] = 0.f; acc[nb][2] = 0.f; acc[nb][3] = 0.f;
        }
        gemm_tile(XH + r0 * 64, XL + r0 * 64, W2H, W2L, g, t, sg, acc);
        __syncthreads();
        {
            float2* sa = (float2*)smem + r0 * 64;
#pragma unroll
            for (int nb = 0; nb < 16; nb++) {
                unsigned d = (unsigned)(4 * nb + t) ^ sg;
                sa[d]       = make_float2(acc[nb][0], acc[nb][1]);
                sa[512 + d] = make_float2(acc[nb][2], acc[nb][3]);
            }
        }
        __syncthreads();
        {
            int row = tid >> 1, hf = tid & 1;
            int r = min(base + row, Nt - 1);
            unsigned s = (unsigned)((row & 7) << 2);
            const float2* rp = (const float2*)smem + row * 64;
            float2 vv[32];
            float s1 = 0.f, s2 = 0.f;
#pragma unroll
            for (int w = 0; w < 32; w++) {
                float2 e = rp[(unsigned)(32 * hf + w) ^ s];
                vv[w] = e;
                s1 += e.x + e.y;
                s2 += e.x * e.x + e.y * e.y;
            }
            s1 += __shfl_xor_sync(0xffffffffu, s1, 1);
            s2 += __shfl_xor_sync(0xffffffffu, s2, 1);
            float mu = s1 * 0.0078125f;
            float rs = rsqrtf(s2 * 0.0078125f - mu * mu + EPSn);
            if (base + row < Nt) {
                const float4* idp = (const float4*)(tfeat + (size_t)r * 128) + hf * 16;
                float4* dst = (float4*)(out + (size_t)r * 128) + hf * 16;
#pragma unroll
                for (int q = 0; q < 16; q++) {
                    int c = hf * 64 + 4 * q;
                    float4 idv = idp[q];
                    float2 e0 = vv[2 * q], e1 = vv[2 * q + 1];
                    float4 o;
                    o.x = fmaxf((e0.x - mu) * rs * ps[512 + c]     + ps[640 + c]     + idv.x, 0.f);
                    o.y = fmaxf((e0.y - mu) * rs * ps[512 + c + 1] + ps[640 + c + 1] + idv.y, 0.f);
                    o.z = fmaxf((e1.x - mu) * rs * ps[512 + c + 2] + ps[640 + c + 2] + idv.z, 0.f);
                    o.w = fmaxf((e1.y - mu) * rs * ps[512 + c + 3] + ps[640 + c + 3] + idv.w, 0.f);
                    dst[q] = o;
                }
            }
        }
        __syncthreads();
    }
}

// ---------------------------------------------------------------------------
// launch
// ---------------------------------------------------------------------------
extern "C" void kernel_launch(void* const* d_in, const int* in_sizes, int n_in,
                              void* d_out, int out_size) {
    const float* context_feat = (const float*)d_in[0];
    const float* target_feat  = (const float*)d_in[1];
    const float* context_pose = (const float*)d_in[2];
    const float* target_pose  = (const float*)d_in[3];
    const int*   hi    = (const int*)d_in[4];
    const int*   wi    = (const int*)d_in[5];
    const float* W_in  = (const float*)d_in[6];
    const float* W_rp  = (const float*)d_in[7];
    const float* b_rp  = (const float*)d_in[8];
    const float* W_c1  = (const float*)d_in[9];
    const float* g_ctx = (const float*)d_in[10];
    const float* be_ctx= (const float*)d_in[11];
    const float* W_c2  = (const float*)d_in[12];
    const float* g_n   = (const float*)d_in[13];
    const float* be_n  = (const float*)d_in[14];
    const float* W_m1  = (const float*)d_in[15];
    const float* g_m1  = (const float*)d_in[16];
    const float* be_m1 = (const float*)d_in[17];
    const float* W_m2  = (const float*)d_in[18];
    const float* g_m2  = (const float*)d_in[19];
    const float* be_m2 = (const float*)d_in[20];

    int Nt = in_sizes[1] / 128;
    int E  = in_sizes[4];
    float* out = (float*)d_out;

    const int SM1 = 4 * 32768;                    // 131072
    const int SM2 = 6 * 32768 + 896 * 4;          // 200192
    const int SM3 = 6 * 32768 + 768 * 4;          // 199680

    cudaFuncSetAttribute(k1mma, cudaFuncAttributeMaxDynamicSharedMemorySize, SM1);
    cudaFuncSetAttribute(k2mma, cudaFuncAttributeMaxDynamicSharedMemorySize, SM2);
    cudaFuncSetAttribute(k3mma, cudaFuncAttributeMaxDynamicSharedMemorySize, SM3);

    k0_prep<<<128, 256>>>(W_in, W_c1, W_c2, W_m1, W_m2);
    k1mma<<<148, 256, SM1>>>(target_feat, Nt);
    k2mma<<<148, 256, SM2>>>(context_feat, context_pose, target_pose, hi, wi,
                             W_rp, b_rp, g_ctx, be_ctx, E);
    k3mma<<<148, 256, SM3>>>(target_feat, g_n, be_n, g_m1, be_m1, g_m2, be_m2,
                             out, Nt);
}

// round 8
// speedup vs baseline: 1.7799x; 1.4954x over previous
#include <cuda_runtime.h>
#include <cuda_bf16.h>

#define EPSn 1e-5f

// ---------------- device scratch (no allocs allowed) ----------------
__device__ float g_tf[100000 * 128];
// fragment-ordered weights: uint index ((nb*KS+ks)*32+lane)*2+rho, bf16 half=delta
__device__ __align__(256) __nv_bfloat16 g_W1f_h[128 * 256];   // KS=16
__device__ __align__(256) __nv_bfloat16 g_W1f_l[128 * 256];
__device__ __align__(256) __nv_bfloat16 g_W2f_h[128 * 128];   // KS=8
__device__ __align__(256) __nv_bfloat16 g_W2f_l[128 * 128];
__device__ __align__(256) __nv_bfloat16 g_Winf_h[128 * 128];  // KS=8
__device__ __align__(256) __nv_bfloat16 g_Winf_l[128 * 128];
// permw-ordered (k3)
__device__ __align__(256) __nv_bfloat16 g_Wm1t_h[128 * 128];
__device__ __align__(256) __nv_bfloat16 g_Wm1t_l[128 * 128];
__device__ __align__(256) __nv_bfloat16 g_Wm2t_h[128 * 128];
__device__ __align__(256) __nv_bfloat16 g_Wm2t_l[128 * 128];

__device__ __forceinline__ unsigned permw(unsigned w) {
    return (w & ~7u) | ((w & 3u) << 1) | ((w >> 2) & 1u);
}

__device__ __forceinline__ void mma_bf16(float* c, unsigned a0, unsigned a1,
                                         unsigned a2, unsigned a3,
                                         unsigned b0, unsigned b1) {
    asm volatile(
        "mma.sync.aligned.m16n8k16.row.col.f32.bf16.bf16.f32 "
        "{%0,%1,%2,%3},{%4,%5,%6,%7},{%8,%9},{%0,%1,%2,%3};"
        : "+f"(c[0]), "+f"(c[1]), "+f"(c[2]), "+f"(c[3])
        : "r"(a0), "r"(a1), "r"(a2), "r"(a3), "r"(b0), "r"(b1));
}

__device__ __forceinline__ void split2(float a, float b, unsigned& h, unsigned& l) {
    __nv_bfloat16 ah = __float2bfloat16(a);
    __nv_bfloat16 bh = __float2bfloat16(b);
    __nv_bfloat16 al = __float2bfloat16(a - __bfloat162float(ah));
    __nv_bfloat16 bl = __float2bfloat16(b - __bfloat162float(bh));
    __nv_bfloat162 hp; hp.x = ah; hp.y = bh;
    __nv_bfloat162 lp; lp.x = al; lp.y = bl;
    h = *(unsigned*)&hp;
    l = *(unsigned*)&lp;
}

// ---------------------------------------------------------------------------
// K0: weight prep
// ---------------------------------------------------------------------------
extern "C" __global__ void k0_prep(const float* __restrict__ Win,
                                   const float* __restrict__ W1,
                                   const float* __restrict__ W2,
                                   const float* __restrict__ Wm1,
                                   const float* __restrict__ Wm2) {
    int i = blockIdx.x * blockDim.x + threadIdx.x;
    if (i < 128 * 256) {          // W1: n-out 128, k 256, KS=16
        int n = i >> 8, k = i & 255;
        int nb = n >> 3, g = n & 7, ks = k >> 4, kc = k & 15;
        int wp = kc >> 1, dlt = kc & 1, t = wp & 3, rho = wp >> 2;
        int b = (((nb * 16 + ks) * 32 + 4 * g + t) * 2 + rho) * 2 + dlt;
        float v = W1[k * 128 + n];
        __nv_bfloat16 h = __float2bfloat16(v);
        g_W1f_h[b] = h;
        g_W1f_l[b] = __float2bfloat16(v - __bfloat162float(h));
    }
    if (i < 128 * 128) {
        int n = i >> 7, k = i & 127;
        int nb = n >> 3, g = n & 7, ks = k >> 4, kc = k & 15;
        int wp = kc >> 1, dlt = kc & 1, t = wp & 3, rho = wp >> 2;
        int b = (((nb * 8 + ks) * 32 + 4 * g + t) * 2 + rho) * 2 + dlt;
        float v2 = W2[k * 128 + n];
        __nv_bfloat16 h2 = __float2bfloat16(v2);
        g_W2f_h[b] = h2;
        g_W2f_l[b] = __float2bfloat16(v2 - __bfloat162float(h2));
        float vi = Win[k * 128 + n];
        __nv_bfloat16 hi_ = __float2bfloat16(vi);
        g_Winf_h[b] = hi_;
        g_Winf_l[b] = __float2bfloat16(vi - __bfloat162float(hi_));

        int d = n * 128 + (int)((permw((unsigned)(k >> 1)) << 1) | (unsigned)(k & 1));
        float v3 = Wm1[k * 128 + n];
        __nv_bfloat16 h3 = __float2bfloat16(v3);
        g_Wm1t_h[d] = h3;
        g_Wm1t_l[d] = __float2bfloat16(v3 - __bfloat162float(h3));
        float v4 = Wm2[k * 128 + n];
        __nv_bfloat16 h4 = __float2bfloat16(v4);
        g_Wm2t_h[d] = h4;
        g_Wm2t_l[d] = __float2bfloat16(v4 - __bfloat162float(h4));
    }
}

// ---------------------------------------------------------------------------
// kzero: g_tf = 0 (so the W_in projection becomes a red.add too)
// ---------------------------------------------------------------------------
extern "C" __global__ void kzero(int n4) {
    float4 z = make_float4(0.f, 0.f, 0.f, 0.f);
    for (int i = blockIdx.x * blockDim.x + threadIdx.x; i < n4;
         i += gridDim.x * blockDim.x)
        ((float4*)g_tf)[i] = z;
}

// ---------------------------------------------------------------------------
// kfused: barrier-free warp-independent edge pipeline + W_in projection.
// Work unit = 16 edges (or 16 target rows) per warp. A operands in registers,
// W1/W2 resident in smem (frag order), W_in frags from global (L2-hot).
// ---------------------------------------------------------------------------
extern "C" __global__ void __launch_bounds__(256, 1)
kfused(const float* __restrict__ cfeat, const float* __restrict__ cpose,
       const float* __restrict__ tpose, const int* __restrict__ hiA,
       const int* __restrict__ wiA, const float* __restrict__ Wrp,
       const float* __restrict__ brp, const float* __restrict__ gcv,
       const float* __restrict__ bcv, const float* __restrict__ tfeat,
       int E, int Nt) {
    extern __shared__ unsigned smu[];
    unsigned* W1H = smu;              // 16384
    unsigned* W1L = W1H + 16384;      // 16384
    unsigned* W2H = W1L + 16384;      // 8192
    unsigned* W2L = W2H + 8192;       // 8192
    float* wrp_s = (float*)(W2L + 8192);  // 512
    float* brp_s = wrp_s + 512;           // 128
    float* gc_s  = brp_s + 128;           // 128
    float* bc_s  = gc_s + 128;            // 128

    const int tid = threadIdx.x;
    {
        const unsigned* a = (const unsigned*)g_W1f_h;
        const unsigned* b = (const unsigned*)g_W1f_l;
        for (int i = tid; i < 16384; i += 256) { W1H[i] = a[i]; W1L[i] = b[i]; }
        const unsigned* c = (const unsigned*)g_W2f_h;
        const unsigned* d = (const unsigned*)g_W2f_l;
        for (int i = tid; i < 8192; i += 256) { W2H[i] = c[i]; W2L[i] = d[i]; }
    }
    for (int i = tid; i < 512; i += 256) wrp_s[i] = Wrp[i];
    if (tid < 128) { brp_s[tid] = brp[tid]; gc_s[tid] = gcv[tid]; bc_s[tid] = bcv[tid]; }
    __syncthreads();   // the only block barrier

    const int warp = tid >> 5, lane = tid & 31;
    const int g = lane >> 2, t = lane & 3;
    const int gw = blockIdx.x * 8 + warp;
    const int nw = gridDim.x * 8;
    const int nbe = (E + 15) >> 4;
    const int nbr = (Nt + 15) >> 4;

    for (int b16 = gw; b16 < nbe + nbr; b16 += nw) {
        if (b16 < nbe) {
            // ================= edge block of 16 =================
            const int eb = b16 << 4;
            const int e0 = eb + g, e8 = eb + g + 8;
            const bool v0 = e0 < E, v8 = e8 < E;
            const int h0i = hiA[min(e0, E - 1)], h8i = hiA[min(e8, E - 1)];
            const int w0i = wiA[min(e0, E - 1)], w8i = wiA[min(e8, E - 1)];

            float acc[16][4];
#pragma unroll
            for (int nb = 0; nb < 16; nb++) {
                acc[nb][0] = 0.f; acc[nb][1] = 0.f; acc[nb][2] = 0.f; acc[nb][3] = 0.f;
            }

            // ---- GEMM1 k-half0: cfeat gather straight into A frags ----
            {
                unsigned Ah[8][4], Al[8][4];
                const float2* c0p = (const float2*)(cfeat + (size_t)h0i * 128);
                const float2* c8p = (const float2*)(cfeat + (size_t)h8i * 128);
#pragma unroll
                for (int j = 0; j < 8; j++) {
                    float2 f0a = c0p[8 * j + t];
                    float2 f8a = c8p[8 * j + t];
                    float2 f0b = c0p[8 * j + t + 4];
                    float2 f8b = c8p[8 * j + t + 4];
                    split2(f0a.x, f0a.y, Ah[j][0], Al[j][0]);
                    split2(f8a.x, f8a.y, Ah[j][1], Al[j][1]);
                    split2(f0b.x, f0b.y, Ah[j][2], Al[j][2]);
                    split2(f8b.x, f8b.y, Ah[j][3], Al[j][3]);
                }
#pragma unroll
                for (int j = 0; j < 8; j++) {
#pragma unroll
                    for (int nb = 0; nb < 16; nb++) {
                        unsigned off = (unsigned)(((nb * 16 + j) * 32 + lane) * 2);
                        uint2 Bh = *(const uint2*)(W1H + off);
                        uint2 Bl = *(const uint2*)(W1L + off);
                        mma_bf16(acc[nb], Ah[j][0], Ah[j][1], Ah[j][2], Ah[j][3], Bh.x, Bh.y);
                        mma_bf16(acc[nb], Al[j][0], Al[j][1], Al[j][2], Al[j][3], Bh.x, Bh.y);
                        mma_bf16(acc[nb], Ah[j][0], Ah[j][1], Ah[j][2], Ah[j][3], Bl.x, Bl.y);
                    }
                }
            }

            // ---- GEMM1 k-half1: relpose MLP straight into A frags ----
            {
                float4 cpg = *(const float4*)(cpose + 4 * (size_t)h0i);
                float4 tpg = *(const float4*)(tpose + 4 * (size_t)w0i);
                float4 cp8 = *(const float4*)(cpose + 4 * (size_t)h8i);
                float4 tp8 = *(const float4*)(tpose + 4 * (size_t)w8i);
                float dg0 = cpg.x - tpg.x, dg1 = cpg.y - tpg.y;
                float dg2 = cpg.z - tpg.z, dg3 = cpg.w - tpg.w;
                float d80 = cp8.x - tp8.x, d81 = cp8.y - tp8.y;
                float d82 = cp8.z - tp8.z, d83 = cp8.w - tp8.w;

                unsigned Ah[8][4], Al[8][4];
#pragma unroll
                for (int j = 0; j < 8; j++) {
                    int cA = 16 * j + 2 * t;
#pragma unroll
                    for (int p = 0; p < 2; p++) {   // p=0: cA pair, p=1: cA+8 pair
                        int c = cA + 8 * p;
                        float w0a = wrp_s[c],       w0b = wrp_s[c + 1];
                        float w1a = wrp_s[128 + c], w1b = wrp_s[129 + c];
                        float w2a = wrp_s[256 + c], w2b = wrp_s[257 + c];
                        float w3a = wrp_s[384 + c], w3b = wrp_s[385 + c];
                        float ba_ = brp_s[c], bb_ = brp_s[c + 1];
                        float rg0 = fmaxf(ba_ + dg0 * w0a + dg1 * w1a + dg2 * w2a + dg3 * w3a, 0.f);
                        float rg1 = fmaxf(bb_ + dg0 * w0b + dg1 * w1b + dg2 * w2b + dg3 * w3b, 0.f);
                        float r80 = fmaxf(ba_ + d80 * w0a + d81 * w1a + d82 * w2a + d83 * w3a, 0.f);
                        float r81 = fmaxf(bb_ + d80 * w0b + d81 * w1b + d82 * w2b + d83 * w3b, 0.f);
                        split2(rg0, rg1, Ah[j][2 * p], Al[j][2 * p]);
                        split2(r80, r81, Ah[j][2 * p + 1], Al[j][2 * p + 1]);
                    }
                }
#pragma unroll
                for (int j = 0; j < 8; j++) {
#pragma unroll
                    for (int nb = 0; nb < 16; nb++) {
                        unsigned off = (unsigned)(((nb * 16 + 8 + j) * 32 + lane) * 2);
                        uint2 Bh = *(const uint2*)(W1H + off);
                        uint2 Bl = *(const uint2*)(W1L + off);
                        mma_bf16(acc[nb], Ah[j][0], Ah[j][1], Ah[j][2], Ah[j][3], Bh.x, Bh.y);
                        mma_bf16(acc[nb], Al[j][0], Al[j][1], Al[j][2], Al[j][3], Bh.x, Bh.y);
                        mma_bf16(acc[nb], Ah[j][0], Ah[j][1], Ah[j][2], Ah[j][3], Bl.x, Bl.y);
                    }
                }
            }

            // ---- GN + relu -> h (stays in registers, already frag-shaped) ----
            unsigned hh[16], hl[16], hh8[16], hl8[16];
            {
                float s1a = 0.f, s2a = 0.f, s1b = 0.f, s2b = 0.f;
#pragma unroll
                for (int nb = 0; nb < 16; nb++) {
                    s1a += acc[nb][0] + acc[nb][1];
                    s2a += acc[nb][0] * acc[nb][0] + acc[nb][1] * acc[nb][1];
                    s1b += acc[nb][2] + acc[nb][3];
                    s2b += acc[nb][2] * acc[nb][2] + acc[nb][3] * acc[nb][3];
                }
#pragma unroll
                for (int off = 1; off <= 2; off <<= 1) {
                    s1a += __shfl_xor_sync(0xffffffffu, s1a, off);
                    s2a += __shfl_xor_sync(0xffffffffu, s2a, off);
                    s1b += __shfl_xor_sync(0xffffffffu, s1b, off);
                    s2b += __shfl_xor_sync(0xffffffffu, s2b, off);
                }
                float mua = s1a * 0.0078125f;
                float rsa = rsqrtf(s2a * 0.0078125f - mua * mua + EPSn);
                float mub = s1b * 0.0078125f;
                float rsb = rsqrtf(s2b * 0.0078125f - mub * mub + EPSn);
#pragma unroll
                for (int nb = 0; nb < 16; nb++) {
                    int c0 = 8 * nb + 2 * t;
                    float ga = gc_s[c0], gb = gc_s[c0 + 1];
                    float ba = bc_s[c0], bb = bc_s[c0 + 1];
                    float h0 = fmaxf((acc[nb][0] - mua) * rsa * ga + ba, 0.f);
                    float h1 = fmaxf((acc[nb][1] - mua) * rsa * gb + bb, 0.f);
                    float h2 = fmaxf((acc[nb][2] - mub) * rsb * ga + ba, 0.f);
                    float h3 = fmaxf((acc[nb][3] - mub) * rsb * gb + bb, 0.f);
                    split2(h0, h1, hh[nb], hl[nb]);
                    split2(h2, h3, hh8[nb], hl8[nb]);
                }
            }

            // ---- GEMM2 (h regs x W2 smem), scatter per output block ----
            float* dst0 = g_tf + (size_t)w0i * 128 + 2 * t;
            float* dst8 = g_tf + (size_t)w8i * 128 + 2 * t;
#pragma unroll
            for (int nb2 = 0; nb2 < 16; nb2++) {
                float a2[4] = {0.f, 0.f, 0.f, 0.f};
#pragma unroll
                for (int j = 0; j < 8; j++) {
                    unsigned off = (unsigned)(((nb2 * 8 + j) * 32 + lane) * 2);
                    uint2 Bh = *(const uint2*)(W2H + off);
                    uint2 Bl = *(const uint2*)(W2L + off);
                    mma_bf16(a2, hh[2 * j], hh8[2 * j], hh[2 * j + 1], hh8[2 * j + 1], Bh.x, Bh.y);
                    mma_bf16(a2, hl[2 * j], hl8[2 * j], hl[2 * j + 1], hl8[2 * j + 1], Bh.x, Bh.y);
                    mma_bf16(a2, hh[2 * j], hh8[2 * j], hh[2 * j + 1], hh8[2 * j + 1], Bl.x, Bl.y);
                }
                if (v0)
                    asm volatile("red.global.add.v2.f32 [%0], {%1,%2};"
                                 :: "l"(dst0 + 8 * nb2), "f"(a2[0]), "f"(a2[1]) : "memory");
                if (v8)
                    asm volatile("red.global.add.v2.f32 [%0], {%1,%2};"
                                 :: "l"(dst8 + 8 * nb2), "f"(a2[2]), "f"(a2[3]) : "memory");
            }
        } else {
            // ================= row block of 16 (W_in projection) =================
            const int rb = (b16 - nbe) << 4;
            const int r0r = rb + g, r8r = rb + g + 8;
            const bool v0 = r0r < Nt, v8 = r8r < Nt;
            const float2* c0p = (const float2*)(tfeat + (size_t)min(r0r, Nt - 1) * 128);
            const float2* c8p = (const float2*)(tfeat + (size_t)min(r8r, Nt - 1) * 128);

            unsigned Ah[8][4], Al[8][4];
#pragma unroll
            for (int j = 0; j < 8; j++) {
                float2 f0a = c0p[8 * j + t];
                float2 f8a = c8p[8 * j + t];
                float2 f0b = c0p[8 * j + t + 4];
                float2 f8b = c8p[8 * j + t + 4];
                split2(f0a.x, f0a.y, Ah[j][0], Al[j][0]);
                split2(f8a.x, f8a.y, Ah[j][1], Al[j][1]);
                split2(f0b.x, f0b.y, Ah[j][2], Al[j][2]);
                split2(f8b.x, f8b.y, Ah[j][3], Al[j][3]);
            }

            const unsigned* WiH = (const unsigned*)g_Winf_h;
            const unsigned* WiL = (const unsigned*)g_Winf_l;
            float* dst0 = g_tf + (size_t)r0r * 128 + 2 * t;
            float* dst8 = g_tf + (size_t)r8r * 128 + 2 * t;
#pragma unroll
            for (int nb = 0; nb < 16; nb++) {
                float a2[4] = {0.f, 0.f, 0.f, 0.f};
#pragma unroll
                for (int j = 0; j < 8; j++) {
                    unsigned off = (unsigned)(((nb * 8 + j) * 32 + lane) * 2);
                    uint2 Bh = *(const uint2*)(WiH + off);
                    uint2 Bl = *(const uint2*)(WiL + off);
                    mma_bf16(a2, Ah[j][0], Ah[j][1], Ah[j][2], Ah[j][3], Bh.x, Bh.y);
                    mma_bf16(a2, Al[j][0], Al[j][1], Al[j][2], Al[j][3], Bh.x, Bh.y);
                    mma_bf16(a2, Ah[j][0], Ah[j][1], Ah[j][2], Ah[j][3], Bl.x, Bl.y);
                }
                if (v0)
                    asm volatile("red.global.add.v2.f32 [%0], {%1,%2};"
                                 :: "l"(dst0 + 8 * nb), "f"(a2[0]), "f"(a2[1]) : "memory");
                if (v8)
                    asm volatile("red.global.add.v2.f32 [%0], {%1,%2};"
                                 :: "l"(dst8 + 8 * nb), "f"(a2[2]), "f"(a2[3]) : "memory");
            }
        }
    }
}

// ---------------------------------------------------------------------------
// K3 (mma, permw layout): GN -> W_m1 -> GN -> W_m2 -> GN + identity + relu.
// (unchanged from R7 — validated)
// ---------------------------------------------------------------------------
__device__ __forceinline__ void gemm_tile(const unsigned* __restrict__ xh,
                                          const unsigned* __restrict__ xl,
                                          const unsigned* __restrict__ WH,
                                          const unsigned* __restrict__ WL,
                                          int g, int t, unsigned sg,
                                          float acc[16][4]) {
#pragma unroll
    for (int ks = 0; ks < 8; ks++) {
        unsigned o = (unsigned)(8 * ks + 2 * t) ^ sg;
        uint2 Ah0 = *(const uint2*)(xh + o);
        uint2 Ah1 = *(const uint2*)(xh + 512 + o);
        uint2 Al0 = *(const uint2*)(xl + o);
        uint2 Al1 = *(const uint2*)(xl + 512 + o);
#pragma unroll
        for (int nb = 0; nb < 16; nb++) {
            const unsigned* wh = WH + (8 * nb + g) * 64;
            const unsigned* wl = WL + (8 * nb + g) * 64;
            uint2 Bh = *(const uint2*)(wh + o);
            uint2 Bl = *(const uint2*)(wl + o);
            mma_bf16(acc[nb], Ah0.x, Ah1.x, Ah0.y, Ah1.y, Bh.x, Bh.y);
            mma_bf16(acc[nb], Al0.x, Al1.x, Al0.y, Al1.y, Bh.x, Bh.y);
            mma_bf16(acc[nb], Ah0.x, Ah1.x, Ah0.y, Ah1.y, Bl.x, Bl.y);
        }
    }
}

__device__ __forceinline__ void stageW(unsigned* dstH, unsigned* dstL,
                                       const __nv_bfloat16* srcH,
                                       const __nv_bfloat16* srcL, int tid) {
    const unsigned* sh = (const unsigned*)srcH;
    const unsigned* sl = (const unsigned*)srcL;
    for (int i = tid; i < 8192; i += 256) {
        int n = i >> 6, w = i & 63;
        int d = n * 64 + (w ^ ((n & 7) << 2));
        dstH[d] = sh[i];
        dstL[d] = sl[i];
    }
}

extern "C" __global__ void __launch_bounds__(256, 1)
k3mma(const float* __restrict__ tfeat,
      const float* __restrict__ gn,  const float* __restrict__ ben,
      const float* __restrict__ g1,  const float* __restrict__ b1,
      const float* __restrict__ g2,  const float* __restrict__ b2,
      float* __restrict__ out, int Nt) {
    extern __shared__ char smem[];
    unsigned* XH  = (unsigned*)smem;
    unsigned* XL  = XH + 8192;
    unsigned* W1H = XL + 8192;
    unsigned* W1L = W1H + 8192;
    unsigned* W2H = W1L + 8192;
    unsigned* W2L = W2H + 8192;
    float* ps = (float*)(W2L + 8192);

    const int tid = threadIdx.x;
    stageW(W1H, W1L, g_Wm1t_h, g_Wm1t_l, tid);
    stageW(W2H, W2L, g_Wm2t_h, g_Wm2t_l, tid);
    if (tid < 128) {
        ps[tid]       = gn[tid];  ps[128 + tid] = ben[tid];
        ps[256 + tid] = g1[tid];  ps[384 + tid] = b1[tid];
        ps[512 + tid] = g2[tid];  ps[640 + tid] = b2[tid];
    }

    const int warp = tid >> 5, lane = tid & 31;
    const int g = lane >> 2, t = lane & 3;
    const int r0 = warp * 16 + g;
    const unsigned sg = (unsigned)(g << 2);
    const int ntiles = (Nt + 127) >> 7;
    float acc[16][4];

    __syncthreads();

    for (int tile = blockIdx.x; tile < ntiles; tile += gridDim.x) {
        const int base = tile << 7;
        {
            int row = tid >> 1, hf = tid & 1;
            int r = min(base + row, Nt - 1);
            const float4* src = (const float4*)(g_tf + (size_t)r * 128) + hf * 16;
            float v[64];
            float s1 = 0.f, s2 = 0.f;
#pragma unroll
            for (int q = 0; q < 16; q++) {
                float4 f = src[q];
                v[4 * q] = f.x; v[4 * q + 1] = f.y; v[4 * q + 2] = f.z; v[4 * q + 3] = f.w;
                s1 += f.x + f.y + f.z + f.w;
                s2 += f.x * f.x + f.y * f.y + f.z * f.z + f.w * f.w;
            }
            s1 += __shfl_xor_sync(0xffffffffu, s1, 1);
            s2 += __shfl_xor_sync(0xffffffffu, s2, 1);
            float mu = s1 * 0.0078125f;
            float rs = rsqrtf(s2 * 0.0078125f - mu * mu + EPSn);
            unsigned s = (unsigned)((row & 7) << 2);
            unsigned* xh = XH + row * 64;
            unsigned* xl = XL + row * 64;
#pragma unroll
            for (int q = 0; q < 16; q++) {
                int c = hf * 64 + 4 * q;
                float a0 = fmaxf((v[4 * q]     - mu) * rs * ps[c]     + ps[128 + c], 0.f);
                float a1 = fmaxf((v[4 * q + 1] - mu) * rs * ps[c + 1] + ps[129 + c], 0.f);
                float a2 = fmaxf((v[4 * q + 2] - mu) * rs * ps[c + 2] + ps[130 + c], 0.f);
                float a3 = fmaxf((v[4 * q + 3] - mu) * rs * ps[c + 3] + ps[131 + c], 0.f);
                unsigned h0, l0, h1, l1;
                split2(a0, a1, h0, l0);
                split2(a2, a3, h1, l1);
                unsigned w0 = (unsigned)(hf * 32 + 2 * q);
                unsigned d0 = permw(w0) ^ s, d1 = permw(w0 + 1) ^ s;
                xh[d0] = h0; xh[d1] = h1;
                xl[d0] = l0; xl[d1] = l1;
            }
        }
        __syncwarp();

#pragma unroll
        for (int nb = 0; nb < 16; nb++) {
            acc[nb][0] = 0.f; acc[nb][1] = 0.f; acc[nb][2] = 0.f; acc[nb][3] = 0.f;
        }
        gemm_tile(XH + r0 * 64, XL + r0 * 64, W1H, W1L, g, t, sg, acc);
        {
            float s1a = 0.f, s2a = 0.f, s1b = 0.f, s2b = 0.f;
#pragma unroll
            for (int nb = 0; nb < 16; nb++) {
                s1a += acc[nb][0] + acc[nb][1];
                s2a += acc[nb][0] * acc[nb][0] + acc[nb][1] * acc[nb][1];
                s1b += acc[nb][2] + acc[nb][3];
                s2b += acc[nb][2] * acc[nb][2] + acc[nb][3] * acc[nb][3];
            }
#pragma unroll
            for (int off = 1; off <= 2; off <<= 1) {
                s1a += __shfl_xor_sync(0xffffffffu, s1a, off);
                s2a += __shfl_xor_sync(0xffffffffu, s2a, off);
                s1b += __shfl_xor_sync(0xffffffffu, s1b, off);
                s2b += __shfl_xor_sync(0xffffffffu, s2b, off);
            }
            float mua = s1a * 0.0078125f;
            float rsa = rsqrtf(s2a * 0.0078125f - mua * mua + EPSn);
            float mub = s1b * 0.0078125f;
            float rsb = rsqrtf(s2b * 0.0078125f - mub * mub + EPSn);
            unsigned* xh = XH + r0 * 64;
            unsigned* xl = XL + r0 * 64;
#pragma unroll
            for (int nb = 0; nb < 16; nb++) {
                int c0 = 8 * nb + 2 * t;
                float ga = ps[256 + c0], gb = ps[257 + c0];
                float ba = ps[384 + c0], bb = ps[385 + c0];
                float h0 = fmaxf((acc[nb][0] - mua) * rsa * ga + ba, 0.f);
                float h1 = fmaxf((acc[nb][1] - mua) * rsa * gb + bb, 0.f);
                float h2 = fmaxf((acc[nb][2] - mub) * rsb * ga + ba, 0.f);
                float h3 = fmaxf((acc[nb][3] - mub) * rsb * gb + bb, 0.f);
                unsigned p0, q0, p1, q1;
                split2(h0, h1, p0, q0);
                split2(h2, h3, p1, q1);
                unsigned d = permw((unsigned)(4 * nb + t)) ^ sg;
                xh[d] = p0; xh[512 + d] = p1;
                xl[d] = q0; xl[512 + d] = q1;
            }
        }
        __syncwarp();

#pragma unroll
        for (int nb = 0; nb < 16; nb++) {
            acc[nb][0] = 0.f; acc[nb][1] = 0.f; acc[nb][2] = 0.f; acc[nb][3] = 0.f;
        }
        gemm_tile(XH + r0 * 64, XL + r0 * 64, W2H, W2L, g, t, sg, acc);
        __syncthreads();
        {
            float2* sa = (float2*)smem + r0 * 64;
#pragma unroll
            for (int nb = 0; nb < 16; nb++) {
                unsigned d = (unsigned)(4 * nb + t) ^ sg;
                sa[d]       = make_float2(acc[nb][0], acc[nb][1]);
                sa[512 + d] = make_float2(acc[nb][2], acc[nb][3]);
            }
        }
        __syncthreads();
        {
            int row = tid >> 1, hf = tid & 1;
            int r = min(base + row, Nt - 1);
            unsigned s = (unsigned)((row & 7) << 2);
            const float2* rp = (const float2*)smem + row * 64;
            float2 vv[32];
            float s1 = 0.f, s2 = 0.f;
#pragma unroll
            for (int w = 0; w < 32; w++) {
                float2 e = rp[(unsigned)(32 * hf + w) ^ s];
                vv[w] = e;
                s1 += e.x + e.y;
                s2 += e.x * e.x + e.y * e.y;
            }
            s1 += __shfl_xor_sync(0xffffffffu, s1, 1);
            s2 += __shfl_xor_sync(0xffffffffu, s2, 1);
            float mu = s1 * 0.0078125f;
            float rs = rsqrtf(s2 * 0.0078125f - mu * mu + EPSn);
            if (base + row < Nt) {
                const float4* idp = (const float4*)(tfeat + (size_t)r * 128) + hf * 16;
                float4* dst = (float4*)(out + (size_t)r * 128) + hf * 16;
#pragma unroll
                for (int q = 0; q < 16; q++) {
                    int c = hf * 64 + 4 * q;
                    float4 idv = idp[q];
                    float2 e0 = vv[2 * q], e1 = vv[2 * q + 1];
                    float4 o;
                    o.x = fmaxf((e0.x - mu) * rs * ps[512 + c]     + ps[640 + c]     + idv.x, 0.f);
                    o.y = fmaxf((e0.y - mu) * rs * ps[512 + c + 1] + ps[640 + c + 1] + idv.y, 0.f);
                    o.z = fmaxf((e1.x - mu) * rs * ps[512 + c + 2] + ps[640 + c + 2] + idv.z, 0.f);
                    o.w = fmaxf((e1.y - mu) * rs * ps[512 + c + 3] + ps[640 + c + 3] + idv.w, 0.f);
                    dst[q] = o;
                }
            }
        }
        __syncthreads();
    }
}

// ---------------------------------------------------------------------------
// launch
// ---------------------------------------------------------------------------
extern "C" void kernel_launch(void* const* d_in, const int* in_sizes, int n_in,
                              void* d_out, int out_size) {
    const float* context_feat = (const float*)d_in[0];
    const float* target_feat  = (const float*)d_in[1];
    const float* context_pose = (const float*)d_in[2];
    const float* target_pose  = (const float*)d_in[3];
    const int*   hi    = (const int*)d_in[4];
    const int*   wi    = (const int*)d_in[5];
    const float* W_in  = (const float*)d_in[6];
    const float* W_rp  = (const float*)d_in[7];
    const float* b_rp  = (const float*)d_in[8];
    const float* W_c1  = (const float*)d_in[9];
    const float* g_ctx = (const float*)d_in[10];
    const float* be_ctx= (const float*)d_in[11];
    const float* W_c2  = (const float*)d_in[12];
    const float* g_n   = (const float*)d_in[13];
    const float* be_n  = (const float*)d_in[14];
    const float* W_m1  = (const float*)d_in[15];
    const float* g_m1  = (const float*)d_in[16];
    const float* be_m1 = (const float*)d_in[17];
    const float* W_m2  = (const float*)d_in[18];
    const float* g_m2  = (const float*)d_in[19];
    const float* be_m2 = (const float*)d_in[20];

    int Nt = in_sizes[1] / 128;
    int E  = in_sizes[4];
    float* out = (float*)d_out;

    const int SMF = (16384 * 2 + 8192 * 2) * 4 + 896 * 4;   // 200192
    const int SM3 = 6 * 32768 + 768 * 4;                    // 199680

    cudaFuncSetAttribute(kfused, cudaFuncAttributeMaxDynamicSharedMemorySize, SMF);
    cudaFuncSetAttribute(k3mma,  cudaFuncAttributeMaxDynamicSharedMemorySize, SM3);

    k0_prep<<<128, 256>>>(W_in, W_c1, W_c2, W_m1, W_m2);
    kzero<<<296, 256>>>(Nt * 32);
    kfused<<<148, 256, SMF>>>(context_feat, context_pose, target_pose, hi, wi,
                              W_rp, b_rp, g_ctx, be_ctx, target_feat, E, Nt);
    k3mma<<<148, 256, SM3>>>(target_feat, g_n, be_n, g_m1, be_m1, g_m2, be_m2,
                             out, Nt);
}